// round 3
// baseline (speedup 1.0000x reference)
#include <cuda_runtime.h>
#include <cstdint>

// Problem shapes (fixed by the dataset)
constexpr int Bdim = 8;     // batch
constexpr int T    = 512;   // tokens
constexpr int D    = 1024;  // model dim (both contraction and output)
constexpr int KSEL = 2;     // experts per batch
constexpr int E    = 64;    // expert count

// Tiling
constexpr int BM = 128;
constexpr int BN = 128;
constexpr int BK = 32;
constexpr int THREADS = 256;         // 8 warps: 4 in M x 2 in N, warp tile 32x64
constexpr int AS_STRIDE = BK + 4;    // 36 floats -> conflict-free A frag loads
constexpr int BS_STRIDE = BN + 8;    // 136 floats -> conflict-free B frag loads
constexpr int SMEM_FLOATS = 2 * BM * AS_STRIDE + 2 * BK * BS_STRIDE; // 17920
constexpr int SMEM_BYTES  = SMEM_FLOATS * 4;                          // 71680

__device__ __forceinline__ void cp16(float* smem_ptr, const float* gmem_ptr) {
    uint32_t s = (uint32_t)__cvta_generic_to_shared(smem_ptr);
    asm volatile("cp.async.cg.shared.global [%0], [%1], 16;" :: "r"(s), "l"(gmem_ptr));
}

__device__ __forceinline__ uint32_t f2tf32(float f) {
    uint32_t r;
    asm("cvt.rna.tf32.f32 %0, %1;" : "=r"(r) : "f"(f));
    return r;
}

__device__ __forceinline__ void mma_tf32(float* c, const uint32_t* a, const uint32_t* b) {
    asm volatile(
        "mma.sync.aligned.m16n8k8.row.col.f32.tf32.tf32.f32 "
        "{%0,%1,%2,%3}, {%4,%5,%6,%7}, {%8,%9}, {%0,%1,%2,%3};\n"
        : "+f"(c[0]), "+f"(c[1]), "+f"(c[2]), "+f"(c[3])
        : "r"(a[0]), "r"(a[1]), "r"(a[2]), "r"(a[3]), "r"(b[0]), "r"(b[1]));
}

// idx dtype auto-detect: JAX with x64 disabled silently downcasts the
// reference's int64 to int32, so the harness buffer is most likely int32.
// If it really were little-endian int64 (values < 64), every odd int32 word
// (high half) of the first 8 entries would be 0; for an int32 buffer those
// words are live idx values (uniform in [0,64)), so P(false int64 detect)
// = (1/64)^8 ~ 3e-15.
__device__ __forceinline__ int load_expert_idx(const void* idx_raw, int pos) {
    const int* p32 = (const int*)idx_raw;
    bool is64 = true;
    #pragma unroll
    for (int j = 1; j < 16; j += 2) is64 &= (p32[j] == 0);
    int e = is64 ? (int)p32[2 * pos] : p32[pos];
    return min(max(e, 0), E - 1);
}

extern __shared__ float smem[];

__global__ void __launch_bounds__(THREADS, 1)
expertbank_kernel(const float* __restrict__ x,
                  const float* __restrict__ w,
                  const float* __restrict__ Wb,
                  const float* __restrict__ bb,
                  const void*  __restrict__ idx,
                  float* __restrict__ out)
{
    const int tn = blockIdx.x;   // N tile (0..7)
    const int tm = blockIdx.y;   // M tile (0..3)
    const int b  = blockIdx.z;   // batch

    const int tid  = threadIdx.x;
    const int lane = tid & 31;
    const int warp = tid >> 5;
    const int wm = warp & 3;     // warp row (M), 4 warps
    const int wn = warp >> 2;    // warp col (N), 2 warps

    const float* xblk = x + ((size_t)b * T + (size_t)tm * BM) * D;

    float* As0 = smem;                         // 2 x [BM][AS_STRIDE]
    float* Bs0 = smem + 2 * BM * AS_STRIDE;    // 2 x [BK][BS_STRIDE]

    float out_acc[2][8][4];
    #pragma unroll
    for (int mi = 0; mi < 2; ++mi)
        #pragma unroll
        for (int ni = 0; ni < 8; ++ni)
            #pragma unroll
            for (int j = 0; j < 4; ++j)
                out_acc[mi][ni][j] = 0.f;

    const int KT = D / BK;  // 32

    for (int ke = 0; ke < KSEL; ++ke) {
        const int   e   = load_expert_idx(idx, b * KSEL + ke);
        const float wgt = w[b * KSEL + ke];
        const float* Wp = Wb + (size_t)e * D * D + (size_t)tn * BN;
        const float* bp = bb + (size_t)e * D + (size_t)tn * BN;

        float acc[2][8][4];
        #pragma unroll
        for (int mi = 0; mi < 2; ++mi)
            #pragma unroll
            for (int ni = 0; ni < 8; ++ni)
                #pragma unroll
                for (int j = 0; j < 4; ++j)
                    acc[mi][ni][j] = 0.f;

        auto load_ab = [&](int kt, int buf) {
            float* Ad = As0 + buf * (BM * AS_STRIDE);
            const float* Ag = xblk + kt * BK;
            #pragma unroll
            for (int i = 0; i < 4; ++i) {
                int lin = tid + i * THREADS;          // 0..1023
                int m  = lin >> 3;                    // 128 rows
                int kv = (lin & 7) << 2;              // 8 float4 per row
                cp16(Ad + m * AS_STRIDE + kv, Ag + (size_t)m * D + kv);
            }
            float* Bd = Bs0 + buf * (BK * BS_STRIDE);
            const float* Bg = Wp + (size_t)kt * BK * D;
            #pragma unroll
            for (int i = 0; i < 4; ++i) {
                int lin = tid + i * THREADS;
                int k  = lin >> 5;                    // 32 rows
                int nv = (lin & 31) << 2;             // 32 float4 per row
                cp16(Bd + k * BS_STRIDE + nv, Bg + (size_t)k * D + nv);
            }
        };

        // prologue
        load_ab(0, 0);
        asm volatile("cp.async.commit_group;" ::: "memory");

        for (int kt = 0; kt < KT; ++kt) {
            asm volatile("cp.async.wait_group 0;" ::: "memory");
            __syncthreads();
            if (kt + 1 < KT) {
                load_ab(kt + 1, (kt + 1) & 1);
                asm volatile("cp.async.commit_group;" ::: "memory");
            }
            const float* Ab = As0 + (kt & 1) * (BM * AS_STRIDE);
            const float* Bb = Bs0 + (kt & 1) * (BK * BS_STRIDE);

            #pragma unroll
            for (int kk = 0; kk < BK / 8; ++kk) {
                uint32_t af[2][4];
                #pragma unroll
                for (int mi = 0; mi < 2; ++mi) {
                    int r = wm * 32 + mi * 16 + (lane >> 2);
                    int c = kk * 8 + (lane & 3);
                    const float* A0 = Ab + r * AS_STRIDE + c;
                    af[mi][0] = f2tf32(A0[0]);
                    af[mi][1] = f2tf32(A0[8 * AS_STRIDE]);
                    af[mi][2] = f2tf32(A0[4]);
                    af[mi][3] = f2tf32(A0[8 * AS_STRIDE + 4]);
                }
                uint32_t bf[8][2];
                #pragma unroll
                for (int ni = 0; ni < 8; ++ni) {
                    int c  = wn * 64 + ni * 8 + (lane >> 2);
                    int k0 = kk * 8 + (lane & 3);
                    const float* B0 = Bb + k0 * BS_STRIDE + c;
                    bf[ni][0] = f2tf32(B0[0]);
                    bf[ni][1] = f2tf32(B0[4 * BS_STRIDE]);
                }
                #pragma unroll
                for (int mi = 0; mi < 2; ++mi)
                    #pragma unroll
                    for (int ni = 0; ni < 8; ++ni)
                        mma_tf32(acc[mi][ni], af[mi], bf[ni]);
            }
        }
        __syncthreads();

        // epilogue: out_acc += w * relu(acc + bias)
        #pragma unroll
        for (int mi = 0; mi < 2; ++mi) {
            #pragma unroll
            for (int ni = 0; ni < 8; ++ni) {
                int col = wn * 64 + ni * 8 + (lane & 3) * 2;
                float bias0 = bp[col];
                float bias1 = bp[col + 1];
                out_acc[mi][ni][0] += wgt * fmaxf(acc[mi][ni][0] + bias0, 0.f);
                out_acc[mi][ni][1] += wgt * fmaxf(acc[mi][ni][1] + bias1, 0.f);
                out_acc[mi][ni][2] += wgt * fmaxf(acc[mi][ni][2] + bias0, 0.f);
                out_acc[mi][ni][3] += wgt * fmaxf(acc[mi][ni][3] + bias1, 0.f);
            }
        }
    }

    // final store (covers the whole tile exactly once)
    float* ob = out + ((size_t)b * T + (size_t)tm * BM) * D + (size_t)tn * BN;
    #pragma unroll
    for (int mi = 0; mi < 2; ++mi) {
        #pragma unroll
        for (int ni = 0; ni < 8; ++ni) {
            int r0 = wm * 32 + mi * 16 + (lane >> 2);
            int c  = wn * 64 + ni * 8 + (lane & 3) * 2;
            float2 v0 = make_float2(out_acc[mi][ni][0], out_acc[mi][ni][1]);
            float2 v1 = make_float2(out_acc[mi][ni][2], out_acc[mi][ni][3]);
            *reinterpret_cast<float2*>(&ob[(size_t)r0 * D + c])       = v0;
            *reinterpret_cast<float2*>(&ob[(size_t)(r0 + 8) * D + c]) = v1;
        }
    }
}

extern "C" void kernel_launch(void* const* d_in, const int* in_sizes, int n_in,
                              void* d_out, int out_size) {
    const float* x   = (const float*)d_in[0];      // (B,T,D)
    const float* w   = (const float*)d_in[1];      // (B,K)
    const float* Wb  = (const float*)d_in[2];      // (E,D,D)
    const float* bb  = (const float*)d_in[3];      // (E,D)
    const void*  idx = (const void*)d_in[4];       // (B,K) int32 (or int64) — auto-detected
    float* out = (float*)d_out;                    // (B,T,D) fp32

    cudaFuncSetAttribute(expertbank_kernel,
                         cudaFuncAttributeMaxDynamicSharedMemorySize, SMEM_BYTES);

    dim3 grid(D / BN, T / BM, Bdim);  // (8, 4, 8) = 256 blocks
    expertbank_kernel<<<grid, THREADS, SMEM_BYTES>>>(x, w, Wb, bb, idx, out);
}